// round 1
// baseline (speedup 1.0000x reference)
#include <cuda_runtime.h>

#define AALPHA 0.42f
#define IMG_H 1024
#define IMG_W 1024
#define NIMG 48   // 16 batches * 3 masks

__device__ float g_scores[NIMG];
__device__ float g_weights[NIMG];

// accurate-enough fast sigmoid: 1/(1+2^(-x*log2e)), err ~1e-6
__device__ __forceinline__ float fsigmoid(float x) {
    float e;
    asm("ex2.approx.f32 %0, %1;" : "=f"(e) : "f"(-1.4426950408889634f * x));
    float r;
    asm("rcp.approx.f32 %0, %1;" : "=f"(r) : "f"(1.0f + e));
    return r;
}

__device__ __forceinline__ float fsqrt_approx(float x) {
    float r;
    asm("sqrt.approx.f32 %0, %1;" : "=f"(r) : "f"(x));
    return r;
}

__global__ void zero_scores_kernel() {
    if (threadIdx.x < NIMG) g_scores[threadIdx.x] = 0.0f;
}

// ---------------------------------------------------------------------------
// Score pass: per image, accumulate
//   ALPHA * sum(edge) + (1-ALPHA)/49 * sum( cnt(p) * (m - localmean)^2 )
// where edge = sqrt(gx^2+gy^2) + 0.5|lap| (3x3, zero pad),
// localmean = (7x7 truncated window sum)/49, cnt = coverage count.
// Tile 32x32 + halo 3, block (32,8), each thread 4 consecutive rows.
// ---------------------------------------------------------------------------
__global__ __launch_bounds__(256) void score_kernel(const float* __restrict__ logits) {
    __shared__ float sm[38 * 39];   // sigmoid tile w/ halo, pitch 39 (conflict-free)
    __shared__ float sh[38 * 33];   // horizontal 7-sums, pitch 33

    const int img = blockIdx.z;
    const int tx0 = blockIdx.x * 32;
    const int ty0 = blockIdx.y * 32;
    const int tid = threadIdx.x + threadIdx.y * 32;
    const float* base = logits + (size_t)img * (IMG_H * IMG_W);

    // ---- load sigmoid(logits) tile with halo 3, zero outside image ----
    #pragma unroll
    for (int it = 0; it < 6; ++it) {
        int i = tid + it * 256;
        if (i < 38 * 38) {
            int ly = i / 38;
            int lx = i - ly * 38;
            int gy = ty0 + ly - 3;
            int gx = tx0 + lx - 3;
            float v = 0.0f;
            if ((unsigned)gy < IMG_H && (unsigned)gx < IMG_W)
                v = fsigmoid(base[gy * IMG_W + gx]);
            sm[ly * 39 + lx] = v;
        }
    }
    __syncthreads();

    // ---- horizontal 7-sums: sh[r][c] = sum_{d=0..6} sm[r][c+d], r:0..37, c:0..31
    // each thread slides over 4 consecutive columns ----
    {
        int c0 = (tid & 7) * 4;
        for (int r = tid >> 3; r < 38; r += 32) {
            const float* row = sm + r * 39 + c0;
            float s = row[0] + row[1] + row[2] + row[3] + row[4] + row[5] + row[6];
            float* o = sh + r * 33 + c0;
            o[0] = s;
            s += row[7] - row[0]; o[1] = s;
            s += row[8] - row[1]; o[2] = s;
            s += row[9] - row[2]; o[3] = s;
        }
    }
    __syncthreads();

    const int tx  = threadIdx.x;
    const int oy0 = threadIdx.y * 4;

    // column coverage count (constant per thread)
    const int gxc = tx0 + tx;
    const int cw  = min(gxc, 3) + min(IMG_W - 1 - gxc, 3) + 1;
    const float cwf = (float)cw;

    // vertical 7-sum init (sliding thereafter)
    float vs = 0.0f;
    #pragma unroll
    for (int d = 0; d < 7; ++d) vs += sh[(oy0 + d) * 33 + tx];

    // conv 3x3 register ring (rows oy+2 .. oy+4 local)
    const float* smp = sm + (oy0 + 2) * 39 + (tx + 2);
    float l0 = smp[0], c0v = smp[1], r0 = smp[2];
    smp += 39;
    float l1 = smp[0], c1v = smp[1], r1 = smp[2];

    float acc = 0.0f;
    #pragma unroll
    for (int k = 0; k < 4; ++k) {
        smp += 39;
        float l2 = smp[0], c2v = smp[1], r2 = smp[2];

        float gxv = (l0 - r0) + 2.0f * (l1 - r1) + (l2 - r2);
        float gyv = (l0 + 2.0f * c0v + r0) - (l2 + 2.0f * c2v + r2);
        float lap = c0v + l1 + r1 + c2v - 4.0f * c1v;

        float edge = fsqrt_approx(gxv * gxv + gyv * gyv) + 0.5f * fabsf(lap);

        float mean = vs * (1.0f / 49.0f);
        float d    = c1v - mean;

        int gyr = ty0 + oy0 + k;
        int ch  = min(gyr, 3) + min(IMG_H - 1 - gyr, 3) + 1;
        float cnt = (float)ch * cwf;

        acc += AALPHA * edge + ((1.0f - AALPHA) / 49.0f) * cnt * (d * d);

        // slide register ring + vertical window
        l0 = l1; c0v = c1v; r0 = r1;
        l1 = l2; c1v = c2v; r1 = r2;
        if (k < 3) vs += sh[(oy0 + 7 + k) * 33 + tx] - sh[(oy0 + k) * 33 + tx];
    }

    // ---- block reduction + atomic ----
    #pragma unroll
    for (int off = 16; off; off >>= 1)
        acc += __shfl_down_sync(0xffffffffu, acc, off);
    __shared__ float red[8];
    if ((tid & 31) == 0) red[tid >> 5] = acc;
    __syncthreads();
    if (tid < 8) {
        float v = red[tid];
        #pragma unroll
        for (int off = 4; off; off >>= 1)
            v += __shfl_down_sync(0xffu, v, off);
        if (tid == 0) atomicAdd(&g_scores[img], v);
    }
}

// ---------------------------------------------------------------------------
// weights[b,s] = 0.5 * ( score[b,s]/(sum_s score[b,:]+1e-6) + softmax(lw)[s] )
// ---------------------------------------------------------------------------
__global__ void weights_kernel(const float* __restrict__ lw) {
    __shared__ float ss[NIMG];
    __shared__ float soft[3];
    int tid = threadIdx.x;
    if (tid < NIMG) ss[tid] = g_scores[tid];
    if (tid == 0) {
        float a = lw[0], b = lw[1], c = lw[2];
        float m = fmaxf(a, fmaxf(b, c));
        float e0 = expf(a - m), e1 = expf(b - m), e2 = expf(c - m);
        float inv = 1.0f / (e0 + e1 + e2);
        soft[0] = e0 * inv; soft[1] = e1 * inv; soft[2] = e2 * inv;
    }
    __syncthreads();
    if (tid < NIMG) {
        int b = tid / 3;
        int s = tid - b * 3;
        float denom = ss[b * 3] + ss[b * 3 + 1] + ss[b * 3 + 2] + 1e-6f;
        g_weights[tid] = (ss[tid] / denom + soft[s]) * 0.5f;
    }
}

// ---------------------------------------------------------------------------
// fused[b,p] = sum_s logits[b,s,p] * w[b,s]   (float4 vectorized)
// ---------------------------------------------------------------------------
__global__ __launch_bounds__(256) void fuse_kernel(const float* __restrict__ logits,
                                                   float* __restrict__ out) {
    const int N = IMG_H * IMG_W;
    int b = blockIdx.y;
    int i = blockIdx.x * blockDim.x + threadIdx.x;   // over N/4
    float w0 = g_weights[b * 3 + 0];
    float w1 = g_weights[b * 3 + 1];
    float w2 = g_weights[b * 3 + 2];
    const float4* p0 = (const float4*)(logits + (size_t)(b * 3 + 0) * N);
    const float4* p1 = (const float4*)(logits + (size_t)(b * 3 + 1) * N);
    const float4* p2 = (const float4*)(logits + (size_t)(b * 3 + 2) * N);
    float4 a = p0[i], bb = p1[i], cc = p2[i];
    float4 o;
    o.x = a.x * w0 + bb.x * w1 + cc.x * w2;
    o.y = a.y * w0 + bb.y * w1 + cc.y * w2;
    o.z = a.z * w0 + bb.z * w1 + cc.z * w2;
    o.w = a.w * w0 + bb.w * w1 + cc.w * w2;
    ((float4*)out)[(size_t)b * (N / 4) + i] = o;
}

extern "C" void kernel_launch(void* const* d_in, const int* in_sizes, int n_in,
                              void* d_out, int out_size) {
    const float* logits = (const float*)d_in[0];   // (16,3,1024,1024) fp32
    const float* lw     = (const float*)d_in[1];   // (3,) fp32
    float* out          = (float*)d_out;           // (16,1024,1024) fp32

    zero_scores_kernel<<<1, 64>>>();
    score_kernel<<<dim3(32, 32, NIMG), dim3(32, 8)>>>(logits);
    weights_kernel<<<1, 64>>>(lw);
    fuse_kernel<<<dim3((IMG_H * IMG_W / 4) / 256, 16), 256>>>(logits, out);
}

// round 2
// speedup vs baseline: 1.1037x; 1.1037x over previous
#include <cuda_runtime.h>

#define AALPHA 0.42f
#define IMG_H 1024
#define IMG_W 1024
#define NIMG 48     // 16 batches * 3 masks
#define RPB 64      // output rows per block

__device__ float g_scores[NIMG];
__device__ float g_weights[NIMG];

// fast sigmoid: 1/(1+2^(-x*log2e)), err ~1e-7
__device__ __forceinline__ float fsigmoid(float x) {
    float e;
    asm("ex2.approx.f32 %0, %1;" : "=f"(e) : "f"(-1.4426950408889634f * x));
    float r;
    asm("rcp.approx.f32 %0, %1;" : "=f"(r) : "f"(1.0f + e));
    return r;
}
__device__ __forceinline__ float fsqrt_fast(float x) {
    float r; asm("sqrt.approx.f32 %0, %1;" : "=f"(r) : "f"(x)); return r;
}

__global__ void zero_scores_kernel() {
    if (threadIdx.x < NIMG) g_scores[threadIdx.x] = 0.0f;
}

// ---------------------------------------------------------------------------
// score = ALPHA * sum(edge) + (1-ALPHA)/49 * sum( cnt(p) * (m_p - mean_p)^2 )
// edge = sqrt(gx^2+gy^2) + 0.5|lap| (3x3, zero pad)
// mean_p = (7x7 zero-padded window sum)/49, cnt = window coverage count.
//
// Each block: full 1024-wide rows, 64 output rows, vertical register sliding.
// Thread t owns columns 4t..4t+3. Per loaded row: LDG.128 + 4 sigmoid +
// STS.128 + BAR + 3 LDS.128; h-sums slide horizontally in registers;
// vertical 7-window in an 8-deep register ring; conv combos (s,t,c) in a
// 4-deep ring. Unroll-by-8 keeps all ring indices static.
// ---------------------------------------------------------------------------
__global__ __launch_bounds__(256) void score_kernel(const float* __restrict__ logits) {
    __shared__ float rowbuf[2][1032];   // cols -4..1027, data at offset 4
    __shared__ float red[8];

    const int img = blockIdx.y;
    const int y0  = blockIdx.x * RPB;
    const int t   = threadIdx.x;
    const int c0  = t * 4;
    const float* base = logits + (size_t)img * (IMG_H * IMG_W);

    // zero pad columns of both buffers (written once, never overwritten)
    if (t < 16) {
        int b = t >> 3, j = t & 7;
        rowbuf[b][(j < 4) ? j : (1020 + j)] = 0.0f;   // j 4..7 -> 1024..1027
    }

    float hr[8][4];                 // horizontal-7-sum ring (vertical window)
    float rs[4][4], rt[4][4], rc[4][4];  // per-row conv combos ring
    float vs[4] = {0.f, 0.f, 0.f, 0.f};
    #pragma unroll
    for (int k = 0; k < 8; ++k) {
        hr[k][0] = hr[k][1] = hr[k][2] = hr[k][3] = 0.f;
    }
    #pragma unroll
    for (int k = 0; k < 4; ++k) {
        #pragma unroll
        for (int j = 0; j < 4; ++j) { rs[k][j] = 0.f; rt[k][j] = 0.f; rc[k][j] = 0.f; }
    }

    float cwf[4];
    #pragma unroll
    for (int j = 0; j < 4; ++j) {
        int col = c0 + j;
        cwf[j] = (float)(min(col, 3) + min(IMG_W - 1 - col, 3) + 1);
    }

    float acc_e = 0.f, acc_v = 0.f;

    // load rows i=0..69 -> gy = y0-3+i ; output row y = gy-3 for i in [6,70)
    for (int ii = 0; ii < 72; ii += 8) {
        #pragma unroll
        for (int u = 0; u < 8; ++u) {
            const int i  = ii + u;
            const int gy = y0 - 3 + i;

            // 1) load + sigmoid (zeros outside image / past last needed row)
            float m0 = 0.f, m1 = 0.f, m2 = 0.f, m3 = 0.f;
            if ((unsigned)gy < IMG_H && i < 70) {
                const float4 x = *(const float4*)(base + (size_t)gy * IMG_W + c0);
                m0 = fsigmoid(x.x); m1 = fsigmoid(x.y);
                m2 = fsigmoid(x.z); m3 = fsigmoid(x.w);
            }
            float* rb = rowbuf[u & 1];
            *(float4*)(rb + 4 + c0) = make_float4(m0, m1, m2, m3);
            __syncthreads();

            // 2) read cols c0-4 .. c0+7 (12 values, 3 aligned float4)
            const float4 A = *(const float4*)(rb + c0);
            const float4 B = *(const float4*)(rb + c0 + 4);
            const float4 C = *(const float4*)(rb + c0 + 8);

            // horizontal 7-sums for cols c0..c0+3
            float h0 = ((A.y + A.z) + (A.w + B.x)) + ((B.y + B.z) + B.w);
            float h1 = h0 + C.x - A.y;
            float h2 = h1 + C.y - A.z;
            float h3 = h2 + C.z - A.w;

            // vertical window slide: + h(row i) - h(row i-7)
            vs[0] += h0 - hr[(u + 1) & 7][0];
            vs[1] += h1 - hr[(u + 1) & 7][1];
            vs[2] += h2 - hr[(u + 1) & 7][2];
            vs[3] += h3 - hr[(u + 1) & 7][3];
            hr[u][0] = h0; hr[u][1] = h1; hr[u][2] = h2; hr[u][3] = h3;

            // 3) output row y = gy-3 (conv rows from ring: i-4, i-3, i-2)
            if (i >= 6 && i < 70) {
                const int yo = gy - 3;
                const float chf = (float)(min(yo, 3) + min(IMG_H - 1 - yo, 3) + 1);
                const int TT = u & 3, MM = (u + 1) & 3, BB = (u + 2) & 3;
                float rowv = 0.f;
                #pragma unroll
                for (int j = 0; j < 4; ++j) {
                    float gxv = rt[TT][j] + 2.f * rt[MM][j] + rt[BB][j];
                    float gyv = rs[TT][j] - rs[BB][j];
                    float lap = rc[TT][j] + rc[BB][j] + rs[MM][j] - 6.f * rc[MM][j];
                    acc_e += fsqrt_fast(gxv * gxv + gyv * gyv) + 0.5f * fabsf(lap);
                    float d = rc[MM][j] - vs[j] * (1.f / 49.f);
                    rowv += cwf[j] * (d * d);
                }
                acc_v += chf * rowv;
            }

            // 4) store conv combos for row i (slot u&3, overwrites row i-4)
            //    cols c0..c0+3: (l,c,r) from A.w, B.x..B.w, C.x
            const int W = u & 3;
            rs[W][0] = fmaf(2.f, B.x, A.w + B.y); rt[W][0] = A.w - B.y; rc[W][0] = B.x;
            rs[W][1] = fmaf(2.f, B.y, B.x + B.z); rt[W][1] = B.x - B.z; rc[W][1] = B.y;
            rs[W][2] = fmaf(2.f, B.z, B.y + B.w); rt[W][2] = B.y - B.w; rc[W][2] = B.z;
            rs[W][3] = fmaf(2.f, B.w, B.z + C.x); rt[W][3] = B.z - C.x; rc[W][3] = B.w;
        }
    }

    float acc = AALPHA * acc_e + ((1.0f - AALPHA) / 49.0f) * acc_v;

    // block reduction + atomic
    #pragma unroll
    for (int off = 16; off; off >>= 1)
        acc += __shfl_down_sync(0xffffffffu, acc, off);
    if ((t & 31) == 0) red[t >> 5] = acc;
    __syncthreads();
    if (t < 8) {
        float v = red[t];
        #pragma unroll
        for (int off = 4; off; off >>= 1)
            v += __shfl_down_sync(0xffu, v, off);
        if (t == 0) atomicAdd(&g_scores[img], v);
    }
}

// ---------------------------------------------------------------------------
// weights[b,s] = 0.5 * ( score[b,s]/(sum_s score[b,:]+1e-6) + softmax(lw)[s] )
// ---------------------------------------------------------------------------
__global__ void weights_kernel(const float* __restrict__ lw) {
    __shared__ float ss[NIMG];
    __shared__ float soft[3];
    int tid = threadIdx.x;
    if (tid < NIMG) ss[tid] = g_scores[tid];
    if (tid == 0) {
        float a = lw[0], b = lw[1], c = lw[2];
        float m = fmaxf(a, fmaxf(b, c));
        float e0 = expf(a - m), e1 = expf(b - m), e2 = expf(c - m);
        float inv = 1.0f / (e0 + e1 + e2);
        soft[0] = e0 * inv; soft[1] = e1 * inv; soft[2] = e2 * inv;
    }
    __syncthreads();
    if (tid < NIMG) {
        int b = tid / 3;
        int s = tid - b * 3;
        float denom = ss[b * 3] + ss[b * 3 + 1] + ss[b * 3 + 2] + 1e-6f;
        g_weights[tid] = (ss[tid] / denom + soft[s]) * 0.5f;
    }
}

// ---------------------------------------------------------------------------
// fused[b,p] = sum_s logits[b,s,p] * w[b,s]   (float4 vectorized)
// ---------------------------------------------------------------------------
__global__ __launch_bounds__(256) void fuse_kernel(const float* __restrict__ logits,
                                                   float* __restrict__ out) {
    const int N = IMG_H * IMG_W;
    int b = blockIdx.y;
    int i = blockIdx.x * blockDim.x + threadIdx.x;   // over N/4
    float w0 = g_weights[b * 3 + 0];
    float w1 = g_weights[b * 3 + 1];
    float w2 = g_weights[b * 3 + 2];
    const float4* p0 = (const float4*)(logits + (size_t)(b * 3 + 0) * N);
    const float4* p1 = (const float4*)(logits + (size_t)(b * 3 + 1) * N);
    const float4* p2 = (const float4*)(logits + (size_t)(b * 3 + 2) * N);
    float4 a = p0[i], bb = p1[i], cc = p2[i];
    float4 o;
    o.x = a.x * w0 + bb.x * w1 + cc.x * w2;
    o.y = a.y * w0 + bb.y * w1 + cc.y * w2;
    o.z = a.z * w0 + bb.z * w1 + cc.z * w2;
    o.w = a.w * w0 + bb.w * w1 + cc.w * w2;
    ((float4*)out)[(size_t)b * (N / 4) + i] = o;
}

extern "C" void kernel_launch(void* const* d_in, const int* in_sizes, int n_in,
                              void* d_out, int out_size) {
    const float* logits = (const float*)d_in[0];   // (16,3,1024,1024) fp32
    const float* lw     = (const float*)d_in[1];   // (3,) fp32
    float* out          = (float*)d_out;           // (16,1024,1024) fp32

    zero_scores_kernel<<<1, 64>>>();
    score_kernel<<<dim3(IMG_H / RPB, NIMG), 256>>>(logits);
    weights_kernel<<<1, 64>>>(lw);
    fuse_kernel<<<dim3((IMG_H * IMG_W / 4) / 256, 16), 256>>>(logits, out);
}